// round 1
// baseline (speedup 1.0000x reference)
#include <cuda_runtime.h>
#include <math.h>

// Problem constants
#define NLAY 4
#define BQ   2
#define LQ   1024
#define DM   512
#define DIN  1024
#define DSN  16
#define RKQ  32
#define BLQ  (BQ*LQ)          // 2048 token rows

// ---------------- device scratch (static, no runtime alloc) ----------------
__device__ float g_res [BLQ*DM];            // residual accumulator
__device__ float g_xn  [BLQ*DM];            // layernorm output
__device__ float g_x   [BLQ*DM];            // current layer activation
__device__ float g_xz  [2*BLQ*2*DIN];       // per-dir in_proj out: [dir][row][2048]
__device__ float g_xcs [2*BLQ*DIN];         // per-dir conv+silu out
__device__ float g_xdbl[2*BLQ*64];          // per-dir x_proj out (dt|B|C)
__device__ float g_dt  [2*BLQ*DIN];         // per-dir softplus(dt)
__device__ float g_y   [2*BLQ*DIN];         // per-dir scan output (gated)

// ---------------- generic fp32 SGEMM: C[M,N] = A[M,K] * W[N,K]^T ----------------
// A row stride = lda; W packed (row stride K); C row stride N.
// blockIdx.z selects a "direction": pointer offsets aZ/wZ/cZ/biasZ.
// FLIPZ: when z==1, A row m=(b*L+t) is read as (b*L + (L-1-t)).
// ACT==1: add bias[n] then softplus.  BETA==1: C += result.
template<int BM,int BN,int BK,int TM,int TN,int FLIPZ,int ACT,int BETA>
__global__ __launch_bounds__((BM/TM)*(BN/TN))
void gemm_k(const float* __restrict__ A, long long aZ, int lda,
            const float* __restrict__ W, long long wZ,
            const float* __restrict__ bias, long long biasZ,
            float* __restrict__ C, long long cZ,
            int M, int N, int K)
{
    constexpr int THREADS = (BM/TM)*(BN/TN);
    __shared__ float As[BK][BM];
    __shared__ float Ws[BK][BN];

    const int tid = threadIdx.x;
    const int z   = blockIdx.z;
    const float* Ap = A + (long long)z * aZ;
    const float* Wp = W + (long long)z * wZ;
    float*       Cp = C + (long long)z * cZ;
    const int bm = blockIdx.y * BM;
    const int bn = blockIdx.x * BN;
    const bool flip = (FLIPZ != 0) && (z == 1);

    const int tx = tid % (BN/TN);
    const int ty = tid / (BN/TN);

    float acc[TM][TN];
    #pragma unroll
    for (int i = 0; i < TM; i++)
        #pragma unroll
        for (int j = 0; j < TN; j++) acc[i][j] = 0.f;

    for (int k0 = 0; k0 < K; k0 += BK) {
        // load A tile (float4 along K), store transposed As[k][m]
        for (int i = tid; i < BM*BK/4; i += THREADS) {
            int row = i / (BK/4);
            int kc  = (i % (BK/4)) * 4;
            int gm  = bm + row;
            int ar  = flip ? ((gm & ~(LQ-1)) | ((LQ-1) - (gm & (LQ-1)))) : gm;
            const float4 v = *reinterpret_cast<const float4*>(Ap + (long long)ar*lda + k0 + kc);
            As[kc+0][row] = v.x; As[kc+1][row] = v.y;
            As[kc+2][row] = v.z; As[kc+3][row] = v.w;
        }
        // load W tile, store transposed Ws[k][n]
        for (int i = tid; i < BN*BK/4; i += THREADS) {
            int row = i / (BK/4);
            int kc  = (i % (BK/4)) * 4;
            const float4 v = *reinterpret_cast<const float4*>(Wp + (long long)(bn+row)*K + k0 + kc);
            Ws[kc+0][row] = v.x; Ws[kc+1][row] = v.y;
            Ws[kc+2][row] = v.z; Ws[kc+3][row] = v.w;
        }
        __syncthreads();
        #pragma unroll
        for (int k = 0; k < BK; k++) {
            float a[TM], bf[TN];
            #pragma unroll
            for (int i = 0; i < TM; i++) a[i] = As[k][ty*TM + i];
            #pragma unroll
            for (int j = 0; j < TN; j++) bf[j] = Ws[k][tx*TN + j];
            #pragma unroll
            for (int i = 0; i < TM; i++)
                #pragma unroll
                for (int j = 0; j < TN; j++)
                    acc[i][j] = fmaf(a[i], bf[j], acc[i][j]);
        }
        __syncthreads();
    }

    // epilogue
    const float* bp = (ACT == 1) ? (bias + (long long)z * biasZ) : nullptr;
    #pragma unroll
    for (int i = 0; i < TM; i++) {
        int gm = bm + ty*TM + i;
        #pragma unroll
        for (int j = 0; j < TN; j++) {
            int gn = bn + tx*TN + j;
            float v = acc[i][j];
            if (ACT == 1) {
                v += bp[gn];
                v = (v > 20.f) ? v : log1pf(__expf(v));   // softplus
            }
            if (BETA) Cp[(long long)gm*N + gn] += v;
            else      Cp[(long long)gm*N + gn]  = v;
        }
    }
}

// ---------------- pre-layer: residual accumulate + layernorm ----------------
__global__ void preln_k(const float* __restrict__ xin,
                        const float* __restrict__ w, const float* __restrict__ b,
                        int first)
{
    __shared__ float sh[16];
    const int r = blockIdx.x, tid = threadIdx.x;     // 256 threads, 2 elems each
    const float* xr = xin + (long long)r*DM;
    float v0 = xr[tid], v1 = xr[tid+256];
    float* rr = g_res + (long long)r*DM;
    if (first) { rr[tid] = v0; rr[tid+256] = v1; }
    else       { rr[tid] += v0; rr[tid+256] += v1; }
    float s = v0+v1, ss = v0*v0 + v1*v1;
    #pragma unroll
    for (int o = 16; o > 0; o >>= 1) {
        s  += __shfl_xor_sync(0xffffffffu, s,  o);
        ss += __shfl_xor_sync(0xffffffffu, ss, o);
    }
    if ((tid & 31) == 0) { sh[tid>>5] = s; sh[8 + (tid>>5)] = ss; }
    __syncthreads();
    if (tid == 0) {
        float a = 0.f, bb = 0.f;
        for (int i = 0; i < 8; i++) { a += sh[i]; bb += sh[8+i]; }
        sh[0] = a; sh[8] = bb;
    }
    __syncthreads();
    float m    = sh[0] * (1.f/DM);
    float var  = sh[8] * (1.f/DM) - m*m;
    float rstd = rsqrtf(var + 1e-5f);
    g_xn[(long long)r*DM + tid]       = (v0 - m)*rstd*w[tid]     + b[tid];
    g_xn[(long long)r*DM + tid + 256] = (v1 - m)*rstd*w[tid+256] + b[tid+256];
}

// ---------------- final: x + residual, then layernorm -> out ----------------
__global__ void final_k(const float* __restrict__ w, const float* __restrict__ b,
                        float* __restrict__ out)
{
    __shared__ float sh[16];
    const int r = blockIdx.x, tid = threadIdx.x;
    float v0 = g_x[(long long)r*DM + tid]       + g_res[(long long)r*DM + tid];
    float v1 = g_x[(long long)r*DM + tid + 256] + g_res[(long long)r*DM + tid + 256];
    float s = v0+v1, ss = v0*v0 + v1*v1;
    #pragma unroll
    for (int o = 16; o > 0; o >>= 1) {
        s  += __shfl_xor_sync(0xffffffffu, s,  o);
        ss += __shfl_xor_sync(0xffffffffu, ss, o);
    }
    if ((tid & 31) == 0) { sh[tid>>5] = s; sh[8 + (tid>>5)] = ss; }
    __syncthreads();
    if (tid == 0) {
        float a = 0.f, bb = 0.f;
        for (int i = 0; i < 8; i++) { a += sh[i]; bb += sh[8+i]; }
        sh[0] = a; sh[8] = bb;
    }
    __syncthreads();
    float m    = sh[0] * (1.f/DM);
    float var  = sh[8] * (1.f/DM) - m*m;
    float rstd = rsqrtf(var + 1e-5f);
    out[(long long)r*DM + tid]       = (v0 - m)*rstd*w[tid]     + b[tid];
    out[(long long)r*DM + tid + 256] = (v1 - m)*rstd*w[tid+256] + b[tid+256];
}

// ---------------- depthwise causal conv (width 4) + bias + silu ----------------
__global__ void conv_silu_k(const float* __restrict__ cw, const float* __restrict__ cb)
{
    int idx = blockIdx.x * blockDim.x + threadIdx.x;     // 2*BLQ*DIN total
    int dir = idx >> 21;                                  // BLQ*DIN = 2^21
    int rem = idx & ((1<<21) - 1);
    int row = rem >> 10;                                  // token row (b*L + t)
    int c   = rem & (DIN-1);
    int t   = row & (LQ-1);
    const float* base = g_xz + (long long)dir*BLQ*2*DIN;  // xc = cols [0,DIN)
    float acc = cb[dir*DIN + c];
    const float* wc = cw + (dir*DIN + c)*4;
    #pragma unroll
    for (int j = 0; j < 4; j++) {
        int tt = t - 3 + j;
        if (tt >= 0) acc = fmaf(wc[j], base[(long long)(row - 3 + j)*(2*DIN) + c], acc);
    }
    acc = acc / (1.f + __expf(-acc));                     // silu
    g_xcs[(long long)dir*BLQ*DIN + (long long)row*DIN + c] = acc;
}

// ---------------- selective scan: 16 lanes/channel, 2 channels/warp ----------------
__global__ void scan_k(const float* __restrict__ A_log, const float* __restrict__ Dp)
{
    int gtid = blockIdx.x * blockDim.x + threadIdx.x;
    int warp = gtid >> 5;
    int lane = threadIdx.x & 31;
    int half = lane >> 4;
    int n    = lane & 15;
    int ch   = warp*2 + half;                 // 0..4095
    int dir  = ch >> 11;
    int bc   = ch & 2047;
    int b    = bc >> 10;
    int c    = bc & (DIN-1);

    const float An = -__expf(A_log[((long long)dir*DIN + c)*DSN + n]);
    const float Dv = Dp[dir*DIN + c];
    const long long rbase = (long long)b * LQ;

    const float* dtp = g_dt   + (long long)dir*BLQ*DIN   + rbase*DIN   + c;
    const float* up  = g_xcs  + (long long)dir*BLQ*DIN   + rbase*DIN   + c;
    const float* Bp  = g_xdbl + (long long)dir*BLQ*64    + rbase*64    + RKQ + n;
    const float* Cpp = Bp + DSN;
    const float* zp  = g_xz   + (long long)dir*BLQ*2*DIN + rbase*2*DIN + DIN + c;
    float*       yp  = g_y    + (long long)dir*BLQ*DIN   + rbase*DIN   + c;

    float h = 0.f;
    for (int t = 0; t < LQ; t++) {
        float dtv = __ldg(dtp + (long long)t*DIN);
        float uv  = __ldg(up  + (long long)t*DIN);
        float Bn  = __ldg(Bp  + (long long)t*64);
        float Cn  = __ldg(Cpp + (long long)t*64);
        float dA  = __expf(dtv * An);
        h = fmaf(dA, h, dtv*uv*Bn);
        float p = h * Cn;
        p += __shfl_xor_sync(0xffffffffu, p, 8, 16);
        p += __shfl_xor_sync(0xffffffffu, p, 4, 16);
        p += __shfl_xor_sync(0xffffffffu, p, 2, 16);
        p += __shfl_xor_sync(0xffffffffu, p, 1, 16);
        if (n == 0) {
            float zv = __ldg(zp + (long long)t*2*DIN);
            float y  = fmaf(uv, Dv, p);
            y *= zv / (1.f + __expf(-zv));                // * silu(z)
            yp[(long long)t*DIN] = y;
        }
    }
}

// ---------------- host orchestration ----------------
extern "C" void kernel_launch(void* const* d_in, const int* in_sizes, int n_in,
                              void* d_out, int out_size)
{
    const float* x        = (const float*)d_in[0];
    const float* in_w     = (const float*)d_in[1];
    const float* conv_w   = (const float*)d_in[2];
    const float* conv_b   = (const float*)d_in[3];
    const float* xp_w     = (const float*)d_in[4];
    const float* dtp_w    = (const float*)d_in[5];
    const float* dtp_b    = (const float*)d_in[6];
    const float* A_log    = (const float*)d_in[7];
    const float* D_param  = (const float*)d_in[8];
    const float* out_w    = (const float*)d_in[9];
    const float* ln_w     = (const float*)d_in[10];
    const float* ln_b     = (const float*)d_in[11];
    const float* fn_w     = (const float*)d_in[12];
    const float* fn_b     = (const float*)d_in[13];
    float* out = (float*)d_out;

    float *p_xn, *p_x, *p_xz, *p_xcs, *p_xdbl, *p_dt, *p_y;
    cudaGetSymbolAddress((void**)&p_xn,   g_xn);
    cudaGetSymbolAddress((void**)&p_x,    g_x);
    cudaGetSymbolAddress((void**)&p_xz,   g_xz);
    cudaGetSymbolAddress((void**)&p_xcs,  g_xcs);
    cudaGetSymbolAddress((void**)&p_xdbl, g_xdbl);
    cudaGetSymbolAddress((void**)&p_dt,   g_dt);
    cudaGetSymbolAddress((void**)&p_y,    g_y);

    for (int l = 0; l < NLAY; l++) {
        // residual accumulate + layernorm
        preln_k<<<BLQ, 256>>>(l == 0 ? x : p_x, ln_w + l*DM, ln_b + l*DM, l == 0);

        // in_proj (both dirs, dir1 reads flipped xn): xz[d] = xn(flip) @ in_w[l,d]^T
        gemm_k<128,128,8,8,8, 1,0,0><<<dim3(16,16,2), 256>>>(
            p_xn, 0LL, DM,
            in_w + (long long)l*2*2*DIN*DM, (long long)2*DIN*DM,
            nullptr, 0LL,
            p_xz, (long long)BLQ*2*DIN,
            BLQ, 2*DIN, DM);

        // depthwise conv + silu
        conv_silu_k<<<(2*BLQ*DIN)/256, 256>>>(conv_w + l*2*DIN*4, conv_b + l*2*DIN);

        // x_proj: x_dbl[d] = xcs[d] @ xp_w[l,d]^T   (N=64)
        gemm_k<128,64,8,8,4, 0,0,0><<<dim3(1,16,2), 256>>>(
            p_xcs, (long long)BLQ*DIN, DIN,
            xp_w + (long long)l*2*64*DIN, (long long)64*DIN,
            nullptr, 0LL,
            p_xdbl, (long long)BLQ*64,
            BLQ, 64, DIN);

        // dt_proj + bias + softplus: dt[d] = softplus(x_dbl[:, :32] @ dtp_w^T + b)
        gemm_k<128,128,8,8,8, 0,1,0><<<dim3(8,16,2), 256>>>(
            p_xdbl, (long long)BLQ*64, 64,
            dtp_w + (long long)l*2*DIN*RKQ, (long long)DIN*RKQ,
            dtp_b + (long long)l*2*DIN, (long long)DIN,
            p_dt, (long long)BLQ*DIN,
            BLQ, DIN, RKQ);

        // selective scan (+ u*D, * silu(z)) — both dirs, 2048 warps
        scan_k<<<256, 256>>>(A_log + (long long)l*2*DIN*DSN, D_param + l*2*DIN);

        // out_proj: x = y0 @ W0^T + y1 @ W1^T
        gemm_k<128,128,8,8,8, 0,0,0><<<dim3(4,16,1), 256>>>(
            p_y, 0LL, DIN,
            out_w + (long long)l*2*DM*DIN, 0LL,
            nullptr, 0LL,
            p_x, 0LL,
            BLQ, DM, DIN);
        gemm_k<128,128,8,8,8, 0,0,1><<<dim3(4,16,1), 256>>>(
            p_y + (long long)BLQ*DIN, 0LL, DIN,
            out_w + (long long)l*2*DM*DIN + (long long)DM*DIN, 0LL,
            nullptr, 0LL,
            p_x, 0LL,
            BLQ, DM, DIN);
    }

    // x + residual -> final layernorm -> out
    final_k<<<BLQ, 256>>>(fn_w, fn_b, out);
}

// round 2
// speedup vs baseline: 1.1182x; 1.1182x over previous
#include <cuda_runtime.h>
#include <cuda_bf16.h>
#include <math.h>

// Problem constants
#define NLAY 4
#define BQ   2
#define LQ   1024
#define DM   512
#define DIN  1024
#define DSN  16
#define RKQ  32
#define BLQ  (BQ*LQ)          // 2048 token rows

// ---------------- device scratch (static, no runtime alloc) ----------------
__device__ float g_res [BLQ*DM];            // residual accumulator
__device__ float g_xn  [BLQ*DM];            // layernorm output
__device__ float g_x   [BLQ*DM];            // current layer activation
__device__ float g_xz  [2*BLQ*2*DIN];       // per-dir in_proj out: [dir][row][2048]
__device__ float g_xcs [2*BLQ*DIN];         // per-dir conv+silu out
__device__ float g_xdbl[2*BLQ*64];          // per-dir x_proj out (dt|B|C)
__device__ float g_dt  [2*BLQ*DIN];         // per-dir softplus(dt)
__device__ float g_y   [2*BLQ*DIN];         // per-dir scan output (gated)

// ---------------- bf16 split helpers ----------------
__device__ __forceinline__ void bsplit(float x, __nv_bfloat16& h, __nv_bfloat16& l) {
    h = __float2bfloat16_rn(x);
    l = __float2bfloat16_rn(x - __bfloat162float(h));
}

__device__ __forceinline__ void mma16816(float* c, const unsigned* a, const unsigned* b) {
    asm volatile(
        "mma.sync.aligned.m16n8k16.row.col.f32.bf16.bf16.f32 "
        "{%0,%1,%2,%3}, {%4,%5,%6,%7}, {%8,%9}, {%0,%1,%2,%3};\n"
        : "+f"(c[0]), "+f"(c[1]), "+f"(c[2]), "+f"(c[3])
        : "r"(a[0]), "r"(a[1]), "r"(a[2]), "r"(a[3]), "r"(b[0]), "r"(b[1]));
}

// ---------------- tensor-core GEMM with bf16x3 split (fp32-accurate) ----------------
// C[M,N] = sum_seg A_seg[M,K] * W_seg[N,K]^T
// blockIdx.z picks direction (aZ/wZ/cZ/biasZ offsets). FLIPZ: dir1 reads A rows
// time-reversed within each batch of L rows. ACT==1: softplus(v + bias[n]).
template<int WGM,int WGN,int MF,int NF,int BK,int FLIPZ,int ACT,int NSEG>
__global__ __launch_bounds__(WGM*WGN*32)
void gemm_tc(const float* __restrict__ A, long long aZ, long long aSeg, int lda,
             const float* __restrict__ W, long long wZ, long long wSeg,
             const float* __restrict__ bias, long long biasZ,
             float* __restrict__ C, long long cZ,
             int M, int N, int K)
{
    constexpr int BM = WGM*MF*16;
    constexpr int BN = WGN*NF*8;
    constexpr int THREADS = WGM*WGN*32;
    constexpr int LDSH = BK + 2;   // bf16 units; even -> 4B-aligned pair loads

    __shared__ __nv_bfloat16 Ah[BM][LDSH];
    __shared__ __nv_bfloat16 Al[BM][LDSH];
    __shared__ __nv_bfloat16 Wh[BN][LDSH];
    __shared__ __nv_bfloat16 Wl[BN][LDSH];

    const int tid  = threadIdx.x;
    const int z    = blockIdx.z;
    const int bm   = blockIdx.y * BM;
    const int bn   = blockIdx.x * BN;
    const bool flip = (FLIPZ != 0) && (z == 1);

    const int wid  = tid >> 5;
    const int lane = tid & 31;
    const int wm   = (wid / WGN) * MF * 16;
    const int wn   = (wid % WGN) * NF * 8;
    const int lr   = lane >> 2;        // 0..7
    const int lc   = lane & 3;         // 0..3

    float acc[MF][NF][4];
    #pragma unroll
    for (int i = 0; i < MF; i++)
        #pragma unroll
        for (int j = 0; j < NF; j++)
            #pragma unroll
            for (int q = 0; q < 4; q++) acc[i][j][q] = 0.f;

    for (int seg = 0; seg < NSEG; seg++) {
        const float* Ap = A + (long long)z * aZ + (long long)seg * aSeg;
        const float* Wp = W + (long long)z * wZ + (long long)seg * wSeg;

        for (int k0 = 0; k0 < K; k0 += BK) {
            // ---- load + split A tile ----
            for (int i = tid; i < BM*(BK/4); i += THREADS) {
                int row = i / (BK/4);
                int kc  = (i % (BK/4)) * 4;
                int gm  = bm + row;
                int ar  = flip ? ((gm & ~(LQ-1)) | ((LQ-1) - (gm & (LQ-1)))) : gm;
                const float4 v = *reinterpret_cast<const float4*>(Ap + (long long)ar*lda + k0 + kc);
                bsplit(v.x, Ah[row][kc+0], Al[row][kc+0]);
                bsplit(v.y, Ah[row][kc+1], Al[row][kc+1]);
                bsplit(v.z, Ah[row][kc+2], Al[row][kc+2]);
                bsplit(v.w, Ah[row][kc+3], Al[row][kc+3]);
            }
            // ---- load + split W tile ----
            for (int i = tid; i < BN*(BK/4); i += THREADS) {
                int row = i / (BK/4);
                int kc  = (i % (BK/4)) * 4;
                const float4 v = *reinterpret_cast<const float4*>(Wp + (long long)(bn+row)*K + k0 + kc);
                bsplit(v.x, Wh[row][kc+0], Wl[row][kc+0]);
                bsplit(v.y, Wh[row][kc+1], Wl[row][kc+1]);
                bsplit(v.z, Wh[row][kc+2], Wl[row][kc+2]);
                bsplit(v.w, Wh[row][kc+3], Wl[row][kc+3]);
            }
            __syncthreads();

            #pragma unroll
            for (int ks = 0; ks < BK/16; ks++) {
                const int kc0 = ks*16 + lc*2;
                unsigned ah[MF][4], al[MF][4], bh[NF][2], bl[NF][2];
                #pragma unroll
                for (int mf = 0; mf < MF; mf++) {
                    int r0 = wm + mf*16 + lr;
                    ah[mf][0] = *reinterpret_cast<const unsigned*>(&Ah[r0  ][kc0]);
                    ah[mf][1] = *reinterpret_cast<const unsigned*>(&Ah[r0+8][kc0]);
                    ah[mf][2] = *reinterpret_cast<const unsigned*>(&Ah[r0  ][kc0+8]);
                    ah[mf][3] = *reinterpret_cast<const unsigned*>(&Ah[r0+8][kc0+8]);
                    al[mf][0] = *reinterpret_cast<const unsigned*>(&Al[r0  ][kc0]);
                    al[mf][1] = *reinterpret_cast<const unsigned*>(&Al[r0+8][kc0]);
                    al[mf][2] = *reinterpret_cast<const unsigned*>(&Al[r0  ][kc0+8]);
                    al[mf][3] = *reinterpret_cast<const unsigned*>(&Al[r0+8][kc0+8]);
                }
                #pragma unroll
                for (int nf = 0; nf < NF; nf++) {
                    int n0 = wn + nf*8 + lr;
                    bh[nf][0] = *reinterpret_cast<const unsigned*>(&Wh[n0][kc0]);
                    bh[nf][1] = *reinterpret_cast<const unsigned*>(&Wh[n0][kc0+8]);
                    bl[nf][0] = *reinterpret_cast<const unsigned*>(&Wl[n0][kc0]);
                    bl[nf][1] = *reinterpret_cast<const unsigned*>(&Wl[n0][kc0+8]);
                }
                #pragma unroll
                for (int mf = 0; mf < MF; mf++)
                    #pragma unroll
                    for (int nf = 0; nf < NF; nf++) {
                        mma16816(acc[mf][nf], ah[mf], bh[nf]);  // hi*hi
                        mma16816(acc[mf][nf], ah[mf], bl[nf]);  // hi*lo
                        mma16816(acc[mf][nf], al[mf], bh[nf]);  // lo*hi
                    }
            }
            __syncthreads();
        }
    }

    // ---- epilogue ----
    float* Cp = C + (long long)z * cZ;
    const float* bp = (ACT == 1) ? (bias + (long long)z * biasZ) : nullptr;
    #pragma unroll
    for (int mf = 0; mf < MF; mf++) {
        #pragma unroll
        for (int nf = 0; nf < NF; nf++) {
            int gm = bm + wm + mf*16 + lr;
            int gn = bn + wn + nf*8 + lc*2;
            float v0 = acc[mf][nf][0], v1 = acc[mf][nf][1];
            float v2 = acc[mf][nf][2], v3 = acc[mf][nf][3];
            if (ACT == 1) {
                float b0 = bp[gn], b1 = bp[gn+1];
                v0 += b0; v1 += b1; v2 += b0; v3 += b1;
                v0 = (v0 > 20.f) ? v0 : log1pf(__expf(v0));
                v1 = (v1 > 20.f) ? v1 : log1pf(__expf(v1));
                v2 = (v2 > 20.f) ? v2 : log1pf(__expf(v2));
                v3 = (v3 > 20.f) ? v3 : log1pf(__expf(v3));
            }
            Cp[(long long)gm*N + gn]       = v0;
            Cp[(long long)gm*N + gn + 1]   = v1;
            Cp[(long long)(gm+8)*N + gn]   = v2;
            Cp[(long long)(gm+8)*N + gn+1] = v3;
        }
    }
}

// ---------------- pre-layer: residual accumulate + layernorm ----------------
__global__ void preln_k(const float* __restrict__ xin,
                        const float* __restrict__ w, const float* __restrict__ b,
                        int first)
{
    __shared__ float sh[16];
    const int r = blockIdx.x, tid = threadIdx.x;     // 256 threads, 2 elems each
    const float* xr = xin + (long long)r*DM;
    float v0 = xr[tid], v1 = xr[tid+256];
    float* rr = g_res + (long long)r*DM;
    if (first) { rr[tid] = v0; rr[tid+256] = v1; }
    else       { rr[tid] += v0; rr[tid+256] += v1; }
    float s = v0+v1, ss = v0*v0 + v1*v1;
    #pragma unroll
    for (int o = 16; o > 0; o >>= 1) {
        s  += __shfl_xor_sync(0xffffffffu, s,  o);
        ss += __shfl_xor_sync(0xffffffffu, ss, o);
    }
    if ((tid & 31) == 0) { sh[tid>>5] = s; sh[8 + (tid>>5)] = ss; }
    __syncthreads();
    if (tid == 0) {
        float a = 0.f, bb = 0.f;
        for (int i = 0; i < 8; i++) { a += sh[i]; bb += sh[8+i]; }
        sh[0] = a; sh[8] = bb;
    }
    __syncthreads();
    float m    = sh[0] * (1.f/DM);
    float var  = sh[8] * (1.f/DM) - m*m;
    float rstd = rsqrtf(var + 1e-5f);
    g_xn[(long long)r*DM + tid]       = (v0 - m)*rstd*w[tid]     + b[tid];
    g_xn[(long long)r*DM + tid + 256] = (v1 - m)*rstd*w[tid+256] + b[tid+256];
}

// ---------------- final: x + residual, then layernorm -> out ----------------
__global__ void final_k(const float* __restrict__ w, const float* __restrict__ b,
                        float* __restrict__ out)
{
    __shared__ float sh[16];
    const int r = blockIdx.x, tid = threadIdx.x;
    float v0 = g_x[(long long)r*DM + tid]       + g_res[(long long)r*DM + tid];
    float v1 = g_x[(long long)r*DM + tid + 256] + g_res[(long long)r*DM + tid + 256];
    float s = v0+v1, ss = v0*v0 + v1*v1;
    #pragma unroll
    for (int o = 16; o > 0; o >>= 1) {
        s  += __shfl_xor_sync(0xffffffffu, s,  o);
        ss += __shfl_xor_sync(0xffffffffu, ss, o);
    }
    if ((tid & 31) == 0) { sh[tid>>5] = s; sh[8 + (tid>>5)] = ss; }
    __syncthreads();
    if (tid == 0) {
        float a = 0.f, bb = 0.f;
        for (int i = 0; i < 8; i++) { a += sh[i]; bb += sh[8+i]; }
        sh[0] = a; sh[8] = bb;
    }
    __syncthreads();
    float m    = sh[0] * (1.f/DM);
    float var  = sh[8] * (1.f/DM) - m*m;
    float rstd = rsqrtf(var + 1e-5f);
    out[(long long)r*DM + tid]       = (v0 - m)*rstd*w[tid]     + b[tid];
    out[(long long)r*DM + tid + 256] = (v1 - m)*rstd*w[tid+256] + b[tid+256];
}

// ---------------- depthwise causal conv (width 4) + bias + silu ----------------
__global__ void conv_silu_k(const float* __restrict__ cw, const float* __restrict__ cb)
{
    int idx = blockIdx.x * blockDim.x + threadIdx.x;     // 2*BLQ*DIN total
    int dir = idx >> 21;                                  // BLQ*DIN = 2^21
    int rem = idx & ((1<<21) - 1);
    int row = rem >> 10;                                  // token row (b*L + t)
    int c   = rem & (DIN-1);
    int t   = row & (LQ-1);
    const float* base = g_xz + (long long)dir*BLQ*2*DIN;  // xc = cols [0,DIN)
    float acc = cb[dir*DIN + c];
    const float* wc = cw + (dir*DIN + c)*4;
    #pragma unroll
    for (int j = 0; j < 4; j++) {
        int tt = t - 3 + j;
        if (tt >= 0) acc = fmaf(wc[j], base[(long long)(row - 3 + j)*(2*DIN) + c], acc);
    }
    acc = acc / (1.f + __expf(-acc));                     // silu
    g_xcs[(long long)dir*BLQ*DIN + (long long)row*DIN + c] = acc;
}

// ---------------- selective scan: 16 lanes/channel, 2 channels/warp ----------------
__global__ void scan_k(const float* __restrict__ A_log, const float* __restrict__ Dp)
{
    int gtid = blockIdx.x * blockDim.x + threadIdx.x;
    int warp = gtid >> 5;
    int lane = threadIdx.x & 31;
    int half = lane >> 4;
    int n    = lane & 15;
    int ch   = warp*2 + half;                 // 0..4095
    int dir  = ch >> 11;
    int bc   = ch & 2047;
    int b    = bc >> 10;
    int c    = bc & (DIN-1);

    const float An = -__expf(A_log[((long long)dir*DIN + c)*DSN + n]);
    const float Dv = Dp[dir*DIN + c];
    const long long rbase = (long long)b * LQ;

    const float* dtp = g_dt   + (long long)dir*BLQ*DIN   + rbase*DIN   + c;
    const float* up  = g_xcs  + (long long)dir*BLQ*DIN   + rbase*DIN   + c;
    const float* Bp  = g_xdbl + (long long)dir*BLQ*64    + rbase*64    + RKQ + n;
    const float* Cpp = Bp + DSN;
    const float* zp  = g_xz   + (long long)dir*BLQ*2*DIN + rbase*2*DIN + DIN + c;
    float*       yp  = g_y    + (long long)dir*BLQ*DIN   + rbase*DIN   + c;

    float h = 0.f;
    for (int t = 0; t < LQ; t++) {
        float dtv = __ldg(dtp + (long long)t*DIN);
        float uv  = __ldg(up  + (long long)t*DIN);
        float Bn  = __ldg(Bp  + (long long)t*64);
        float Cn  = __ldg(Cpp + (long long)t*64);
        float dA  = __expf(dtv * An);
        h = fmaf(dA, h, dtv*uv*Bn);
        float p = h * Cn;
        p += __shfl_xor_sync(0xffffffffu, p, 8, 16);
        p += __shfl_xor_sync(0xffffffffu, p, 4, 16);
        p += __shfl_xor_sync(0xffffffffu, p, 2, 16);
        p += __shfl_xor_sync(0xffffffffu, p, 1, 16);
        if (n == 0) {
            float zv = __ldg(zp + (long long)t*2*DIN);
            float y  = fmaf(uv, Dv, p);
            y *= zv / (1.f + __expf(-zv));                // * silu(z)
            yp[(long long)t*DIN] = y;
        }
    }
}

// ---------------- host orchestration ----------------
extern "C" void kernel_launch(void* const* d_in, const int* in_sizes, int n_in,
                              void* d_out, int out_size)
{
    const float* x        = (const float*)d_in[0];
    const float* in_w     = (const float*)d_in[1];
    const float* conv_w   = (const float*)d_in[2];
    const float* conv_b   = (const float*)d_in[3];
    const float* xp_w     = (const float*)d_in[4];
    const float* dtp_w    = (const float*)d_in[5];
    const float* dtp_b    = (const float*)d_in[6];
    const float* A_log    = (const float*)d_in[7];
    const float* D_param  = (const float*)d_in[8];
    const float* out_w    = (const float*)d_in[9];
    const float* ln_w     = (const float*)d_in[10];
    const float* ln_b     = (const float*)d_in[11];
    const float* fn_w     = (const float*)d_in[12];
    const float* fn_b     = (const float*)d_in[13];
    float* out = (float*)d_out;

    float *p_xn, *p_x, *p_xz, *p_xcs, *p_xdbl, *p_dt, *p_y;
    cudaGetSymbolAddress((void**)&p_xn,   g_xn);
    cudaGetSymbolAddress((void**)&p_x,    g_x);
    cudaGetSymbolAddress((void**)&p_xz,   g_xz);
    cudaGetSymbolAddress((void**)&p_xcs,  g_xcs);
    cudaGetSymbolAddress((void**)&p_xdbl, g_xdbl);
    cudaGetSymbolAddress((void**)&p_dt,   g_dt);
    cudaGetSymbolAddress((void**)&p_y,    g_y);

    for (int l = 0; l < NLAY; l++) {
        // residual accumulate + layernorm
        preln_k<<<BLQ, 256>>>(l == 0 ? x : p_x, ln_w + l*DM, ln_b + l*DM, l == 0);

        // in_proj (both dirs, dir1 reads flipped xn): xz[d] = xn(flip) @ in_w[l,d]^T
        gemm_tc<4,4,2,4,32, 1,0,1><<<dim3(16,16,2), 512>>>(
            p_xn, 0LL, 0LL, DM,
            in_w + (long long)l*2*2*DIN*DM, (long long)2*DIN*DM, 0LL,
            nullptr, 0LL,
            p_xz, (long long)BLQ*2*DIN,
            BLQ, 2*DIN, DM);

        // depthwise conv + silu
        conv_silu_k<<<(2*BLQ*DIN)/256, 256>>>(conv_w + l*2*DIN*4, conv_b + l*2*DIN);

        // x_proj: x_dbl[d] = xcs[d] @ xp_w[l,d]^T   (N=64)
        gemm_tc<2,2,2,4,32, 0,0,1><<<dim3(1,32,2), 128>>>(
            p_xcs, (long long)BLQ*DIN, 0LL, DIN,
            xp_w + (long long)l*2*64*DIN, (long long)64*DIN, 0LL,
            nullptr, 0LL,
            p_xdbl, (long long)BLQ*64,
            BLQ, 64, DIN);

        // dt_proj + bias + softplus: dt[d] = softplus(x_dbl[:, :32] @ dtp_w^T + b)
        gemm_tc<4,4,2,4,32, 0,1,1><<<dim3(8,16,2), 512>>>(
            p_xdbl, (long long)BLQ*64, 0LL, 64,
            dtp_w + (long long)l*2*DIN*RKQ, (long long)DIN*RKQ, 0LL,
            dtp_b + (long long)l*2*DIN, (long long)DIN,
            p_dt, (long long)BLQ*DIN,
            BLQ, DIN, RKQ);

        // selective scan (+ u*D, * silu(z)) — both dirs, 2048 warps
        scan_k<<<256, 256>>>(A_log + (long long)l*2*DIN*DSN, D_param + l*2*DIN);

        // out_proj: x = y0 @ W0^T + y1 @ W1^T  (fused 2-segment K accumulation)
        gemm_tc<4,4,2,4,32, 0,0,2><<<dim3(4,16,1), 512>>>(
            p_y, 0LL, (long long)BLQ*DIN, DIN,
            out_w + (long long)l*2*DM*DIN, 0LL, (long long)DM*DIN,
            nullptr, 0LL,
            p_x, 0LL,
            BLQ, DM, DIN);
    }

    // x + residual -> final layernorm -> out
    final_k<<<BLQ, 256>>>(fn_w, fn_b, out);
}

// round 3
// speedup vs baseline: 1.7789x; 1.5908x over previous
#include <cuda_runtime.h>
#include <cuda_bf16.h>
#include <math.h>
#include <stdint.h>

// Problem constants
#define NLAY 4
#define BQ   2
#define LQ   1024
#define DM   512
#define DIN  1024
#define DSN  16
#define RKQ  32
#define BLQ  (BQ*LQ)          // 2048 token rows

// ---------------- device scratch (static, no runtime alloc) ----------------
__device__ float g_res [BLQ*DM];
__device__ float g_x   [BLQ*DM];
__device__ float g_xz  [2*BLQ*2*DIN];       // per-dir in_proj out
__device__ float g_xcs [2*BLQ*DIN];         // conv+silu out (fp32 for scan)
__device__ float g_xdbl[2*BLQ*64];          // x_proj out fp32 (scan B,C)
__device__ float g_dt  [2*BLQ*DIN];         // softplus(dt) fp32 (scan)

// bf16 split activations
__device__ __nv_bfloat16 a_xn_h [BLQ*DM],    a_xn_l [BLQ*DM];
__device__ __nv_bfloat16 a_xcs_h[2*BLQ*DIN], a_xcs_l[2*BLQ*DIN];
__device__ __nv_bfloat16 a_xd_h [2*BLQ*64],  a_xd_l [2*BLQ*64];
__device__ __nv_bfloat16 a_y_h  [2*BLQ*DIN], a_y_l  [2*BLQ*DIN];

// bf16 split weights (all layers)
#define SZ_IN  (NLAY*2*2*DIN*DM)
#define SZ_XP  (NLAY*2*64*DIN)
#define SZ_DT  (NLAY*2*DIN*RKQ)
#define SZ_OUT (NLAY*2*DM*DIN)
__device__ __nv_bfloat16 w_in_h [SZ_IN],  w_in_l [SZ_IN];
__device__ __nv_bfloat16 w_xp_h [SZ_XP],  w_xp_l [SZ_XP];
__device__ __nv_bfloat16 w_dt_h [SZ_DT],  w_dt_l [SZ_DT];
__device__ __nv_bfloat16 w_out_h[SZ_OUT], w_out_l[SZ_OUT];

// ---------------- helpers ----------------
__device__ __forceinline__ void bsplit(float x, __nv_bfloat16& h, __nv_bfloat16& l) {
    h = __float2bfloat16_rn(x);
    l = __float2bfloat16_rn(x - __bfloat162float(h));
}

__device__ __forceinline__ uint32_t smem_u32(const void* p) {
    uint32_t a;
    asm("{ .reg .u64 t; cvta.to.shared.u64 t, %1; cvt.u32.u64 %0, t; }" : "=r"(a) : "l"(p));
    return a;
}

__device__ __forceinline__ void cp16(uint32_t dst, const void* src) {
    asm volatile("cp.async.cg.shared.global [%0], [%1], 16;\n" :: "r"(dst), "l"(src));
}

#define LDMX4(R, ADDR) \
    asm volatile("ldmatrix.sync.aligned.m8n8.x4.shared.b16 {%0,%1,%2,%3}, [%4];" \
        : "=r"((R)[0]), "=r"((R)[1]), "=r"((R)[2]), "=r"((R)[3]) : "r"(ADDR))

__device__ __forceinline__ void mma16816(float* c, const unsigned* a, const unsigned* b) {
    asm volatile(
        "mma.sync.aligned.m16n8k16.row.col.f32.bf16.bf16.f32 "
        "{%0,%1,%2,%3}, {%4,%5,%6,%7}, {%8,%9}, {%0,%1,%2,%3};\n"
        : "+f"(c[0]), "+f"(c[1]), "+f"(c[2]), "+f"(c[3])
        : "r"(a[0]), "r"(a[1]), "r"(a[2]), "r"(a[3]), "r"(b[0]), "r"(b[1]));
}

// ---------------- weight split kernel ----------------
__global__ void split_k(const float* __restrict__ src,
                        __nv_bfloat16* __restrict__ h, __nv_bfloat16* __restrict__ l, int n)
{
    for (int i = blockIdx.x*blockDim.x + threadIdx.x; i < n; i += gridDim.x*blockDim.x) {
        float v = src[i];
        __nv_bfloat16 hh, ll; bsplit(v, hh, ll);
        h[i] = hh; l[i] = ll;
    }
}

// ---------------- pipelined bf16x3 tensor-core GEMM ----------------
// C[M,N] = sum_seg A_seg[M,K] * W_seg[N,K]^T, operands pre-split bf16 hi/lo.
// blockIdx.z = direction (aZ/wZ/cZ/biasZ offsets). FLIPZ: dir1 reads A rows
// time-reversed within batch. ACT: softplus(v+bias). WSPLIT: also write bf16 hi/lo C.
template<int WGM,int WGN,int MF,int NF,int FLIPZ,int ACT,int NSEG,int WSPLIT>
__global__ __launch_bounds__(WGM*WGN*32)
void gemm_bf(const __nv_bfloat16* __restrict__ Agh, const __nv_bfloat16* __restrict__ Agl,
             long long aZ, long long aSeg, int lda,
             const __nv_bfloat16* __restrict__ Wgh, const __nv_bfloat16* __restrict__ Wgl,
             long long wZ, long long wSeg,
             const float* __restrict__ bias, long long biasZ,
             float* __restrict__ C, long long cZ,
             __nv_bfloat16* __restrict__ Ch, __nv_bfloat16* __restrict__ Cl,
             int M, int N, int K)
{
    constexpr int BK = 32, LDSH = 40;               // 80B row stride (16B aligned, ldmatrix conflict-free)
    constexpr int BM = WGM*MF*16, BN = WGN*NF*8;
    constexpr int THREADS = WGM*WGN*32;
    constexpr int tileA  = BM*LDSH*2;               // bytes per single A tile (hi or lo)
    constexpr int tileW  = BN*LDSH*2;
    constexpr int stageB = 2*tileA + 2*tileW;

    extern __shared__ char dsm[];
    const uint32_t sb = smem_u32(dsm);

    const int tid  = threadIdx.x;
    const int z    = blockIdx.z;
    const int bm   = blockIdx.y * BM;
    const int bn   = blockIdx.x * BN;
    const bool flip = (FLIPZ != 0) && (z == 1);

    const int wid  = tid >> 5;
    const int lane = tid & 31;
    const int wm   = (wid / WGN) * MF * 16;
    const int wn   = (wid % WGN) * NF * 8;
    const int lr   = lane >> 2;
    const int lc   = lane & 3;

    const int KT    = K / BK;
    const int tiles = KT * NSEG;

    float acc[MF][NF][4];
    #pragma unroll
    for (int i = 0; i < MF; i++)
        #pragma unroll
        for (int j = 0; j < NF; j++)
            #pragma unroll
            for (int q = 0; q < 4; q++) acc[i][j][q] = 0.f;

    // ---- tile loader (cp.async) ----
    auto load_tile = [&](int buf, int it) {
        int seg = it / KT;
        int k0  = (it - seg*KT) * BK;
        const __nv_bfloat16* Ahp = Agh + (long long)z*aZ + (long long)seg*aSeg;
        const __nv_bfloat16* Alp = Agl + (long long)z*aZ + (long long)seg*aSeg;
        const __nv_bfloat16* Whp = Wgh + (long long)z*wZ + (long long)seg*wSeg;
        const __nv_bfloat16* Wlp = Wgl + (long long)z*wZ + (long long)seg*wSeg;
        const uint32_t st = sb + buf*stageB;
        // A tiles: BM rows x 4 chunks of 8 halves
        for (int i = tid; i < BM*4; i += THREADS) {
            int row = i >> 2, kc = (i & 3) * 8;
            int gm = bm + row;
            int ar = flip ? ((gm & ~(LQ-1)) | ((LQ-1) - (gm & (LQ-1)))) : gm;
            long long off = (long long)ar*lda + k0 + kc;
            uint32_t d = st + row*(LDSH*2) + kc*2;
            cp16(d,         Ahp + off);
            cp16(d + tileA, Alp + off);
        }
        // W tiles
        for (int i = tid; i < BN*4; i += THREADS) {
            int row = i >> 2, kc = (i & 3) * 8;
            long long off = (long long)(bn + row)*K + k0 + kc;
            uint32_t d = st + 2*tileA + row*(LDSH*2) + kc*2;
            cp16(d,         Whp + off);
            cp16(d + tileW, Wlp + off);
        }
    };

    load_tile(0, 0);
    asm volatile("cp.async.commit_group;\n");

    for (int it = 0; it < tiles; it++) {
        if (it + 1 < tiles) {
            load_tile((it + 1) & 1, it + 1);
            asm volatile("cp.async.commit_group;\n");
            asm volatile("cp.async.wait_group 1;\n");
        } else {
            asm volatile("cp.async.wait_group 0;\n");
        }
        __syncthreads();

        const uint32_t st = sb + (it & 1)*stageB;
        #pragma unroll
        for (int ks = 0; ks < 2; ks++) {
            unsigned ah[MF][4], al[MF][4], bh[NF][2], bl[NF][2];
            // A fragments
            const int arow = wm + (lane & 15);
            const int acol = ks*16 + ((lane >> 4) << 3);
            #pragma unroll
            for (int mf = 0; mf < MF; mf++) {
                uint32_t ad = st + ((arow + mf*16)*LDSH + acol)*2;
                LDMX4(ah[mf], ad);
                LDMX4(al[mf], ad + tileA);
            }
            // B fragments (pairs of nf per ldmatrix.x4)
            const int brow = wn + ((lane >> 4) << 3) + (lane & 7);
            const int bcol = ks*16 + (((lane >> 3) & 1) << 3);
            #pragma unroll
            for (int nf = 0; nf < NF; nf += 2) {
                uint32_t bd = st + 2*tileA + ((brow + nf*8)*LDSH + bcol)*2;
                unsigned r[4];
                LDMX4(r, bd);
                bh[nf][0] = r[0]; bh[nf][1] = r[1];
                bh[nf+1][0] = r[2]; bh[nf+1][1] = r[3];
                LDMX4(r, bd + tileW);
                bl[nf][0] = r[0]; bl[nf][1] = r[1];
                bl[nf+1][0] = r[2]; bl[nf+1][1] = r[3];
            }
            // three split passes, interleaved for ILP
            #pragma unroll
            for (int mf = 0; mf < MF; mf++)
                #pragma unroll
                for (int nf = 0; nf < NF; nf++)
                    mma16816(acc[mf][nf], ah[mf], bh[nf]);
            #pragma unroll
            for (int mf = 0; mf < MF; mf++)
                #pragma unroll
                for (int nf = 0; nf < NF; nf++)
                    mma16816(acc[mf][nf], ah[mf], bl[nf]);
            #pragma unroll
            for (int mf = 0; mf < MF; mf++)
                #pragma unroll
                for (int nf = 0; nf < NF; nf++)
                    mma16816(acc[mf][nf], al[mf], bh[nf]);
        }
        __syncthreads();
    }

    // ---- epilogue ----
    float* Cp = C + (long long)z * cZ;
    __nv_bfloat16* Chp = WSPLIT ? (Ch + (long long)z * cZ) : nullptr;
    __nv_bfloat16* Clp = WSPLIT ? (Cl + (long long)z * cZ) : nullptr;
    const float* bp = (ACT == 1) ? (bias + (long long)z * biasZ) : nullptr;
    #pragma unroll
    for (int mf = 0; mf < MF; mf++) {
        #pragma unroll
        for (int nf = 0; nf < NF; nf++) {
            int gm = bm + wm + mf*16 + lr;
            int gn = bn + wn + nf*8 + lc*2;
            float v0 = acc[mf][nf][0], v1 = acc[mf][nf][1];
            float v2 = acc[mf][nf][2], v3 = acc[mf][nf][3];
            if (ACT == 1) {
                float b0 = bp[gn], b1 = bp[gn+1];
                v0 += b0; v1 += b1; v2 += b0; v3 += b1;
                v0 = (v0 > 20.f) ? v0 : log1pf(__expf(v0));
                v1 = (v1 > 20.f) ? v1 : log1pf(__expf(v1));
                v2 = (v2 > 20.f) ? v2 : log1pf(__expf(v2));
                v3 = (v3 > 20.f) ? v3 : log1pf(__expf(v3));
            }
            Cp[(long long)gm*N + gn]         = v0;
            Cp[(long long)gm*N + gn + 1]     = v1;
            Cp[(long long)(gm+8)*N + gn]     = v2;
            Cp[(long long)(gm+8)*N + gn + 1] = v3;
            if (WSPLIT) {
                __nv_bfloat16 hh, ll;
                bsplit(v0, hh, ll); Chp[(long long)gm*N+gn]       = hh; Clp[(long long)gm*N+gn]       = ll;
                bsplit(v1, hh, ll); Chp[(long long)gm*N+gn+1]     = hh; Clp[(long long)gm*N+gn+1]     = ll;
                bsplit(v2, hh, ll); Chp[(long long)(gm+8)*N+gn]   = hh; Clp[(long long)(gm+8)*N+gn]   = ll;
                bsplit(v3, hh, ll); Chp[(long long)(gm+8)*N+gn+1] = hh; Clp[(long long)(gm+8)*N+gn+1] = ll;
            }
        }
    }
}

// ---------------- pre-layer: residual accumulate + layernorm -> bf16 split ----------------
__global__ void preln_k(const float* __restrict__ xin,
                        const float* __restrict__ w, const float* __restrict__ b,
                        int first)
{
    __shared__ float sh[16];
    const int r = blockIdx.x, tid = threadIdx.x;
    const float* xr = xin + (long long)r*DM;
    float v0 = xr[tid], v1 = xr[tid+256];
    float* rr = g_res + (long long)r*DM;
    if (first) { rr[tid] = v0; rr[tid+256] = v1; }
    else       { rr[tid] += v0; rr[tid+256] += v1; }
    float s = v0+v1, ss = v0*v0 + v1*v1;
    #pragma unroll
    for (int o = 16; o > 0; o >>= 1) {
        s  += __shfl_xor_sync(0xffffffffu, s,  o);
        ss += __shfl_xor_sync(0xffffffffu, ss, o);
    }
    if ((tid & 31) == 0) { sh[tid>>5] = s; sh[8 + (tid>>5)] = ss; }
    __syncthreads();
    if (tid == 0) {
        float a = 0.f, bb = 0.f;
        for (int i = 0; i < 8; i++) { a += sh[i]; bb += sh[8+i]; }
        sh[0] = a; sh[8] = bb;
    }
    __syncthreads();
    float m    = sh[0] * (1.f/DM);
    float var  = sh[8] * (1.f/DM) - m*m;
    float rstd = rsqrtf(var + 1e-5f);
    float o0 = (v0 - m)*rstd*w[tid]     + b[tid];
    float o1 = (v1 - m)*rstd*w[tid+256] + b[tid+256];
    __nv_bfloat16 hh, ll;
    bsplit(o0, hh, ll); a_xn_h[(long long)r*DM+tid]     = hh; a_xn_l[(long long)r*DM+tid]     = ll;
    bsplit(o1, hh, ll); a_xn_h[(long long)r*DM+tid+256] = hh; a_xn_l[(long long)r*DM+tid+256] = ll;
}

// ---------------- final: x + residual -> layernorm -> out ----------------
__global__ void final_k(const float* __restrict__ w, const float* __restrict__ b,
                        float* __restrict__ out)
{
    __shared__ float sh[16];
    const int r = blockIdx.x, tid = threadIdx.x;
    float v0 = g_x[(long long)r*DM + tid]       + g_res[(long long)r*DM + tid];
    float v1 = g_x[(long long)r*DM + tid + 256] + g_res[(long long)r*DM + tid + 256];
    float s = v0+v1, ss = v0*v0 + v1*v1;
    #pragma unroll
    for (int o = 16; o > 0; o >>= 1) {
        s  += __shfl_xor_sync(0xffffffffu, s,  o);
        ss += __shfl_xor_sync(0xffffffffu, ss, o);
    }
    if ((tid & 31) == 0) { sh[tid>>5] = s; sh[8 + (tid>>5)] = ss; }
    __syncthreads();
    if (tid == 0) {
        float a = 0.f, bb = 0.f;
        for (int i = 0; i < 8; i++) { a += sh[i]; bb += sh[8+i]; }
        sh[0] = a; sh[8] = bb;
    }
    __syncthreads();
    float m    = sh[0] * (1.f/DM);
    float var  = sh[8] * (1.f/DM) - m*m;
    float rstd = rsqrtf(var + 1e-5f);
    out[(long long)r*DM + tid]       = (v0 - m)*rstd*w[tid]     + b[tid];
    out[(long long)r*DM + tid + 256] = (v1 - m)*rstd*w[tid+256] + b[tid+256];
}

// ---------------- depthwise causal conv (width 4) + bias + silu ----------------
__global__ void conv_silu_k(const float* __restrict__ cw, const float* __restrict__ cb)
{
    int idx = blockIdx.x * blockDim.x + threadIdx.x;
    int dir = idx >> 21;
    int rem = idx & ((1<<21) - 1);
    int row = rem >> 10;
    int c   = rem & (DIN-1);
    int t   = row & (LQ-1);
    const float* base = g_xz + (long long)dir*BLQ*2*DIN;
    float acc = cb[dir*DIN + c];
    const float* wc = cw + (dir*DIN + c)*4;
    #pragma unroll
    for (int j = 0; j < 4; j++) {
        int tt = t - 3 + j;
        if (tt >= 0) acc = fmaf(wc[j], base[(long long)(row - 3 + j)*(2*DIN) + c], acc);
    }
    acc = acc / (1.f + __expf(-acc));
    long long o = (long long)dir*BLQ*DIN + (long long)row*DIN + c;
    g_xcs[o] = acc;
    __nv_bfloat16 hh, ll; bsplit(acc, hh, ll);
    a_xcs_h[o] = hh; a_xcs_l[o] = ll;
}

// ---------------- selective scan: 16 lanes/channel, 2 channels/warp ----------------
__global__ void scan_k(const float* __restrict__ A_log, const float* __restrict__ Dp)
{
    int gtid = blockIdx.x * blockDim.x + threadIdx.x;
    int warp = gtid >> 5;
    int lane = threadIdx.x & 31;
    int half = lane >> 4;
    int n    = lane & 15;
    int ch   = warp*2 + half;
    int dir  = ch >> 11;
    int bc   = ch & 2047;
    int b    = bc >> 10;
    int c    = bc & (DIN-1);

    const float An = -__expf(A_log[((long long)dir*DIN + c)*DSN + n]);
    const float Dv = Dp[dir*DIN + c];
    const long long rbase = (long long)b * LQ;

    const float* dtp = g_dt   + (long long)dir*BLQ*DIN   + rbase*DIN   + c;
    const float* up  = g_xcs  + (long long)dir*BLQ*DIN   + rbase*DIN   + c;
    const float* Bp  = g_xdbl + (long long)dir*BLQ*64    + rbase*64    + RKQ + n;
    const float* Cpp = Bp + DSN;
    const float* zp  = g_xz   + (long long)dir*BLQ*2*DIN + rbase*2*DIN + DIN + c;
    long long yo     = (long long)dir*BLQ*DIN + rbase*DIN + c;

    // prefetch t=0
    float dtv = __ldg(dtp), uv = __ldg(up), Bn = __ldg(Bp), Cn = __ldg(Cpp);
    float h = 0.f;
    for (int t = 0; t < LQ; t++) {
        float dtn = 0.f, un = 0.f, Bnn = 0.f, Cnn = 0.f;
        if (t + 1 < LQ) {
            dtn = __ldg(dtp + (long long)(t+1)*DIN);
            un  = __ldg(up  + (long long)(t+1)*DIN);
            Bnn = __ldg(Bp  + (long long)(t+1)*64);
            Cnn = __ldg(Cpp + (long long)(t+1)*64);
        }
        float dA = __expf(dtv * An);
        h = fmaf(dA, h, dtv*uv*Bn);
        float p = h * Cn;
        p += __shfl_xor_sync(0xffffffffu, p, 8, 16);
        p += __shfl_xor_sync(0xffffffffu, p, 4, 16);
        p += __shfl_xor_sync(0xffffffffu, p, 2, 16);
        p += __shfl_xor_sync(0xffffffffu, p, 1, 16);
        if (n == 0) {
            float zv = __ldg(zp + (long long)t*2*DIN);
            float y  = fmaf(uv, Dv, p);
            y *= zv / (1.f + __expf(-zv));
            __nv_bfloat16 hh, ll; bsplit(y, hh, ll);
            a_y_h[yo + (long long)t*DIN] = hh;
            a_y_l[yo + (long long)t*DIN] = ll;
        }
        dtv = dtn; uv = un; Bn = Bnn; Cn = Cnn;
    }
}

// ---------------- host orchestration ----------------
extern "C" void kernel_launch(void* const* d_in, const int* in_sizes, int n_in,
                              void* d_out, int out_size)
{
    const float* x        = (const float*)d_in[0];
    const float* in_w     = (const float*)d_in[1];
    const float* conv_w   = (const float*)d_in[2];
    const float* conv_b   = (const float*)d_in[3];
    const float* xp_w     = (const float*)d_in[4];
    const float* dtp_w    = (const float*)d_in[5];
    const float* dtp_b    = (const float*)d_in[6];
    const float* A_log    = (const float*)d_in[7];
    const float* D_param  = (const float*)d_in[8];
    const float* out_w    = (const float*)d_in[9];
    const float* ln_w     = (const float*)d_in[10];
    const float* ln_b     = (const float*)d_in[11];
    const float* fn_w     = (const float*)d_in[12];
    const float* fn_b     = (const float*)d_in[13];
    float* out = (float*)d_out;

    float *p_x, *p_xz, *p_xcs, *p_xdbl, *p_dt;
    cudaGetSymbolAddress((void**)&p_x,    g_x);
    cudaGetSymbolAddress((void**)&p_xz,   g_xz);
    cudaGetSymbolAddress((void**)&p_xcs,  g_xcs);
    cudaGetSymbolAddress((void**)&p_xdbl, g_xdbl);
    cudaGetSymbolAddress((void**)&p_dt,   g_dt);

    __nv_bfloat16 *pw_in_h, *pw_in_l, *pw_xp_h, *pw_xp_l, *pw_dt_h, *pw_dt_l, *pw_out_h, *pw_out_l;
    __nv_bfloat16 *pa_xn_h, *pa_xn_l, *pa_xcs_h, *pa_xcs_l, *pa_xd_h, *pa_xd_l, *pa_y_h, *pa_y_l;
    cudaGetSymbolAddress((void**)&pw_in_h,  w_in_h);  cudaGetSymbolAddress((void**)&pw_in_l,  w_in_l);
    cudaGetSymbolAddress((void**)&pw_xp_h,  w_xp_h);  cudaGetSymbolAddress((void**)&pw_xp_l,  w_xp_l);
    cudaGetSymbolAddress((void**)&pw_dt_h,  w_dt_h);  cudaGetSymbolAddress((void**)&pw_dt_l,  w_dt_l);
    cudaGetSymbolAddress((void**)&pw_out_h, w_out_h); cudaGetSymbolAddress((void**)&pw_out_l, w_out_l);
    cudaGetSymbolAddress((void**)&pa_xn_h,  a_xn_h);  cudaGetSymbolAddress((void**)&pa_xn_l,  a_xn_l);
    cudaGetSymbolAddress((void**)&pa_xcs_h, a_xcs_h); cudaGetSymbolAddress((void**)&pa_xcs_l, a_xcs_l);
    cudaGetSymbolAddress((void**)&pa_xd_h,  a_xd_h);  cudaGetSymbolAddress((void**)&pa_xd_l,  a_xd_l);
    cudaGetSymbolAddress((void**)&pa_y_h,   a_y_h);   cudaGetSymbolAddress((void**)&pa_y_l,   a_y_l);

    // opt-in smem for the big GEMM configs
    cudaFuncSetAttribute((const void*)gemm_bf<2,4,4,4, 1,0,1,0>, cudaFuncAttributeMaxDynamicSharedMemorySize, 81920);
    cudaFuncSetAttribute((const void*)gemm_bf<2,2,2,4, 0,0,1,1>, cudaFuncAttributeMaxDynamicSharedMemorySize, 40960);
    cudaFuncSetAttribute((const void*)gemm_bf<2,4,4,2, 0,1,1,0>, cudaFuncAttributeMaxDynamicSharedMemorySize, 61440);
    cudaFuncSetAttribute((const void*)gemm_bf<2,4,4,2, 0,0,2,0>, cudaFuncAttributeMaxDynamicSharedMemorySize, 61440);

    // weight split (once per launch)
    split_k<<<1024, 256>>>(in_w,  pw_in_h,  pw_in_l,  SZ_IN);
    split_k<<<512,  256>>>(xp_w,  pw_xp_h,  pw_xp_l,  SZ_XP);
    split_k<<<256,  256>>>(dtp_w, pw_dt_h,  pw_dt_l,  SZ_DT);
    split_k<<<1024, 256>>>(out_w, pw_out_h, pw_out_l, SZ_OUT);

    for (int l = 0; l < NLAY; l++) {
        preln_k<<<BLQ, 256>>>(l == 0 ? x : p_x, ln_w + l*DM, ln_b + l*DM, l == 0);

        // in_proj: xz[d] = xn(flip d) @ in_w[l,d]^T   M=2048 N=2048 K=512
        gemm_bf<2,4,4,4, 1,0,1,0><<<dim3(16,16,2), 256, 81920>>>(
            pa_xn_h, pa_xn_l, 0LL, 0LL, DM,
            pw_in_h + (long long)l*2*2*DIN*DM, pw_in_l + (long long)l*2*2*DIN*DM,
            (long long)2*DIN*DM, 0LL,
            nullptr, 0LL,
            p_xz, (long long)BLQ*2*DIN, nullptr, nullptr,
            BLQ, 2*DIN, DM);

        conv_silu_k<<<(2*BLQ*DIN)/256, 256>>>(conv_w + l*2*DIN*4, conv_b + l*2*DIN);

        // x_proj: x_dbl[d] = xcs[d] @ xp_w^T   M=2048 N=64 K=1024 (+ split out)
        gemm_bf<2,2,2,4, 0,0,1,1><<<dim3(1,32,2), 128, 40960>>>(
            pa_xcs_h, pa_xcs_l, (long long)BLQ*DIN, 0LL, DIN,
            pw_xp_h + (long long)l*2*64*DIN, pw_xp_l + (long long)l*2*64*DIN,
            (long long)64*DIN, 0LL,
            nullptr, 0LL,
            p_xdbl, (long long)BLQ*64, pa_xd_h, pa_xd_l,
            BLQ, 64, DIN);

        // dt_proj: dt[d] = softplus(x_dbl[:, :32] @ dtp_w^T + b)   M=2048 N=1024 K=32
        gemm_bf<2,4,4,2, 0,1,1,0><<<dim3(16,16,2), 256, 61440>>>(
            pa_xd_h, pa_xd_l, (long long)BLQ*64, 0LL, 64,
            pw_dt_h + (long long)l*2*DIN*RKQ, pw_dt_l + (long long)l*2*DIN*RKQ,
            (long long)DIN*RKQ, 0LL,
            dtp_b + (long long)l*2*DIN, (long long)DIN,
            p_dt, (long long)BLQ*DIN, nullptr, nullptr,
            BLQ, DIN, RKQ);

        scan_k<<<256, 256>>>(A_log + (long long)l*2*DIN*DSN, D_param + l*2*DIN);

        // out_proj: x = y0 @ W0^T + y1 @ W1^T   M=2048 N=512 K=1024 x 2 segs
        gemm_bf<2,4,4,2, 0,0,2,0><<<dim3(8,16,1), 256, 61440>>>(
            pa_y_h, pa_y_l, 0LL, (long long)BLQ*DIN, DIN,
            pw_out_h + (long long)l*2*DM*DIN, pw_out_l + (long long)l*2*DM*DIN,
            0LL, (long long)DM*DIN,
            nullptr, 0LL,
            p_x, 0LL, nullptr, nullptr,
            BLQ, DM, DIN);
    }

    final_k<<<BLQ, 256>>>(fn_w, fn_b, out);
}

// round 4
// speedup vs baseline: 2.5260x; 1.4200x over previous
#include <cuda_runtime.h>
#include <cuda_bf16.h>
#include <math.h>
#include <stdint.h>

// Problem constants
#define NLAY 4
#define BQ   2
#define LQ   1024
#define DM   512
#define DIN  1024
#define DSN  16
#define RKQ  32
#define BLQ  (BQ*LQ)          // 2048 token rows

// ---------------- device scratch (static, no runtime alloc) ----------------
__device__ float g_res [BLQ*DM];
__device__ float g_x   [BLQ*DM];
__device__ float g_xz  [2*BLQ*2*DIN];       // per-dir in_proj out
__device__ float g_xcs [2*BLQ*DIN];         // conv+silu out (fp32 for scan)
__device__ float g_xdbl[2*BLQ*64];          // x_proj out fp32 (scan B,C)
__device__ float g_dt  [2*BLQ*DIN];         // softplus(dt) fp32 (scan)

// bf16 split activations
__device__ __nv_bfloat16 a_xn_h [BLQ*DM],    a_xn_l [BLQ*DM];
__device__ __nv_bfloat16 a_xcs_h[2*BLQ*DIN], a_xcs_l[2*BLQ*DIN];
__device__ __nv_bfloat16 a_xd_h [2*BLQ*64],  a_xd_l [2*BLQ*64];
__device__ __nv_bfloat16 a_y_h  [2*BLQ*DIN], a_y_l  [2*BLQ*DIN];

// bf16 split weights (all layers)
#define SZ_IN  (NLAY*2*2*DIN*DM)
#define SZ_XP  (NLAY*2*64*DIN)
#define SZ_DT  (NLAY*2*DIN*RKQ)
#define SZ_OUT (NLAY*2*DM*DIN)
__device__ __nv_bfloat16 w_in_h [SZ_IN],  w_in_l [SZ_IN];
__device__ __nv_bfloat16 w_xp_h [SZ_XP],  w_xp_l [SZ_XP];
__device__ __nv_bfloat16 w_dt_h [SZ_DT],  w_dt_l [SZ_DT];
__device__ __nv_bfloat16 w_out_h[SZ_OUT], w_out_l[SZ_OUT];

// ---------------- helpers ----------------
__device__ __forceinline__ void bsplit(float x, __nv_bfloat16& h, __nv_bfloat16& l) {
    h = __float2bfloat16_rn(x);
    l = __float2bfloat16_rn(x - __bfloat162float(h));
}

__device__ __forceinline__ uint32_t smem_u32(const void* p) {
    uint32_t a;
    asm("{ .reg .u64 t; cvta.to.shared.u64 t, %1; cvt.u32.u64 %0, t; }" : "=r"(a) : "l"(p));
    return a;
}

__device__ __forceinline__ void cp16(uint32_t dst, const void* src) {
    asm volatile("cp.async.cg.shared.global [%0], [%1], 16;\n" :: "r"(dst), "l"(src));
}

#define LDMX4(R, ADDR) \
    asm volatile("ldmatrix.sync.aligned.m8n8.x4.shared.b16 {%0,%1,%2,%3}, [%4];" \
        : "=r"((R)[0]), "=r"((R)[1]), "=r"((R)[2]), "=r"((R)[3]) : "r"(ADDR))

__device__ __forceinline__ void mma16816(float* c, const unsigned* a, const unsigned* b) {
    asm volatile(
        "mma.sync.aligned.m16n8k16.row.col.f32.bf16.bf16.f32 "
        "{%0,%1,%2,%3}, {%4,%5,%6,%7}, {%8,%9}, {%0,%1,%2,%3};\n"
        : "+f"(c[0]), "+f"(c[1]), "+f"(c[2]), "+f"(c[3])
        : "r"(a[0]), "r"(a[1]), "r"(a[2]), "r"(a[3]), "r"(b[0]), "r"(b[1]));
}

// ---------------- weight split kernel ----------------
__global__ void split_k(const float* __restrict__ src,
                        __nv_bfloat16* __restrict__ h, __nv_bfloat16* __restrict__ l, int n)
{
    for (int i = blockIdx.x*blockDim.x + threadIdx.x; i < n; i += gridDim.x*blockDim.x) {
        float v = src[i];
        __nv_bfloat16 hh, ll; bsplit(v, hh, ll);
        h[i] = hh; l[i] = ll;
    }
}

// ---------------- pipelined bf16x3 tensor-core GEMM ----------------
// C[M,N] = sum_seg A_seg[M,K] * W_seg[N,K]^T, operands pre-split bf16 hi/lo.
// blockIdx.z = direction. FLIPZ: dir1 reads A rows time-reversed within batch.
// ACT: softplus(v+bias). WSPLIT: also write bf16 hi/lo C.
template<int WGM,int WGN,int MF,int NF,int FLIPZ,int ACT,int NSEG,int WSPLIT>
__global__ __launch_bounds__(WGM*WGN*32)
void gemm_bf(const __nv_bfloat16* __restrict__ Agh, const __nv_bfloat16* __restrict__ Agl,
             long long aZ, long long aSeg, int lda,
             const __nv_bfloat16* __restrict__ Wgh, const __nv_bfloat16* __restrict__ Wgl,
             long long wZ, long long wSeg,
             const float* __restrict__ bias, long long biasZ,
             float* __restrict__ C, long long cZ,
             __nv_bfloat16* __restrict__ Ch, __nv_bfloat16* __restrict__ Cl,
             int M, int N, int K)
{
    constexpr int BK = 32, LDSH = 40;               // 80B row stride, ldmatrix conflict-free
    constexpr int BM = WGM*MF*16, BN = WGN*NF*8;
    constexpr int THREADS = WGM*WGN*32;
    constexpr int tileA  = BM*LDSH*2;
    constexpr int tileW  = BN*LDSH*2;
    constexpr int stageB = 2*tileA + 2*tileW;

    extern __shared__ char dsm[];
    const uint32_t sb = smem_u32(dsm);

    const int tid  = threadIdx.x;
    const int z    = blockIdx.z;
    const int bm   = blockIdx.y * BM;
    const int bn   = blockIdx.x * BN;
    const bool flip = (FLIPZ != 0) && (z == 1);

    const int wid  = tid >> 5;
    const int lane = tid & 31;
    const int wm   = (wid / WGN) * MF * 16;
    const int wn   = (wid % WGN) * NF * 8;
    const int lr   = lane >> 2;
    const int lc   = lane & 3;

    const int KT    = K / BK;
    const int tiles = KT * NSEG;

    float acc[MF][NF][4];
    #pragma unroll
    for (int i = 0; i < MF; i++)
        #pragma unroll
        for (int j = 0; j < NF; j++)
            #pragma unroll
            for (int q = 0; q < 4; q++) acc[i][j][q] = 0.f;

    auto load_tile = [&](int buf, int it) {
        int seg = it / KT;
        int k0  = (it - seg*KT) * BK;
        const __nv_bfloat16* Ahp = Agh + (long long)z*aZ + (long long)seg*aSeg;
        const __nv_bfloat16* Alp = Agl + (long long)z*aZ + (long long)seg*aSeg;
        const __nv_bfloat16* Whp = Wgh + (long long)z*wZ + (long long)seg*wSeg;
        const __nv_bfloat16* Wlp = Wgl + (long long)z*wZ + (long long)seg*wSeg;
        const uint32_t st = sb + buf*stageB;
        for (int i = tid; i < BM*4; i += THREADS) {
            int row = i >> 2, kc = (i & 3) * 8;
            int gm = bm + row;
            int ar = flip ? ((gm & ~(LQ-1)) | ((LQ-1) - (gm & (LQ-1)))) : gm;
            long long off = (long long)ar*lda + k0 + kc;
            uint32_t d = st + row*(LDSH*2) + kc*2;
            cp16(d,         Ahp + off);
            cp16(d + tileA, Alp + off);
        }
        for (int i = tid; i < BN*4; i += THREADS) {
            int row = i >> 2, kc = (i & 3) * 8;
            long long off = (long long)(bn + row)*K + k0 + kc;
            uint32_t d = st + 2*tileA + row*(LDSH*2) + kc*2;
            cp16(d,         Whp + off);
            cp16(d + tileW, Wlp + off);
        }
    };

    load_tile(0, 0);
    asm volatile("cp.async.commit_group;\n");

    for (int it = 0; it < tiles; it++) {
        if (it + 1 < tiles) {
            load_tile((it + 1) & 1, it + 1);
            asm volatile("cp.async.commit_group;\n");
            asm volatile("cp.async.wait_group 1;\n");
        } else {
            asm volatile("cp.async.wait_group 0;\n");
        }
        __syncthreads();

        const uint32_t st = sb + (it & 1)*stageB;
        #pragma unroll
        for (int ks = 0; ks < 2; ks++) {
            unsigned ah[MF][4], al[MF][4], bh[NF][2], bl[NF][2];
            const int arow = wm + (lane & 15);
            const int acol = ks*16 + ((lane >> 4) << 3);
            #pragma unroll
            for (int mf = 0; mf < MF; mf++) {
                uint32_t ad = st + ((arow + mf*16)*LDSH + acol)*2;
                LDMX4(ah[mf], ad);
                LDMX4(al[mf], ad + tileA);
            }
            const int brow = wn + ((lane >> 4) << 3) + (lane & 7);
            const int bcol = ks*16 + (((lane >> 3) & 1) << 3);
            #pragma unroll
            for (int nf = 0; nf < NF; nf += 2) {
                uint32_t bd = st + 2*tileA + ((brow + nf*8)*LDSH + bcol)*2;
                unsigned r[4];
                LDMX4(r, bd);
                bh[nf][0] = r[0]; bh[nf][1] = r[1];
                bh[nf+1][0] = r[2]; bh[nf+1][1] = r[3];
                LDMX4(r, bd + tileW);
                bl[nf][0] = r[0]; bl[nf][1] = r[1];
                bl[nf+1][0] = r[2]; bl[nf+1][1] = r[3];
            }
            #pragma unroll
            for (int mf = 0; mf < MF; mf++)
                #pragma unroll
                for (int nf = 0; nf < NF; nf++)
                    mma16816(acc[mf][nf], ah[mf], bh[nf]);
            #pragma unroll
            for (int mf = 0; mf < MF; mf++)
                #pragma unroll
                for (int nf = 0; nf < NF; nf++)
                    mma16816(acc[mf][nf], ah[mf], bl[nf]);
            #pragma unroll
            for (int mf = 0; mf < MF; mf++)
                #pragma unroll
                for (int nf = 0; nf < NF; nf++)
                    mma16816(acc[mf][nf], al[mf], bh[nf]);
        }
        __syncthreads();
    }

    float* Cp = C + (long long)z * cZ;
    __nv_bfloat16* Chp = WSPLIT ? (Ch + (long long)z * cZ) : nullptr;
    __nv_bfloat16* Clp = WSPLIT ? (Cl + (long long)z * cZ) : nullptr;
    const float* bp = (ACT == 1) ? (bias + (long long)z * biasZ) : nullptr;
    #pragma unroll
    for (int mf = 0; mf < MF; mf++) {
        #pragma unroll
        for (int nf = 0; nf < NF; nf++) {
            int gm = bm + wm + mf*16 + lr;
            int gn = bn + wn + nf*8 + lc*2;
            float v0 = acc[mf][nf][0], v1 = acc[mf][nf][1];
            float v2 = acc[mf][nf][2], v3 = acc[mf][nf][3];
            if (ACT == 1) {
                float b0 = bp[gn], b1 = bp[gn+1];
                v0 += b0; v1 += b1; v2 += b0; v3 += b1;
                v0 = (v0 > 20.f) ? v0 : log1pf(__expf(v0));
                v1 = (v1 > 20.f) ? v1 : log1pf(__expf(v1));
                v2 = (v2 > 20.f) ? v2 : log1pf(__expf(v2));
                v3 = (v3 > 20.f) ? v3 : log1pf(__expf(v3));
            }
            Cp[(long long)gm*N + gn]         = v0;
            Cp[(long long)gm*N + gn + 1]     = v1;
            Cp[(long long)(gm+8)*N + gn]     = v2;
            Cp[(long long)(gm+8)*N + gn + 1] = v3;
            if (WSPLIT) {
                __nv_bfloat16 hh, ll;
                bsplit(v0, hh, ll); Chp[(long long)gm*N+gn]       = hh; Clp[(long long)gm*N+gn]       = ll;
                bsplit(v1, hh, ll); Chp[(long long)gm*N+gn+1]     = hh; Clp[(long long)gm*N+gn+1]     = ll;
                bsplit(v2, hh, ll); Chp[(long long)(gm+8)*N+gn]   = hh; Clp[(long long)(gm+8)*N+gn]   = ll;
                bsplit(v3, hh, ll); Chp[(long long)(gm+8)*N+gn+1] = hh; Clp[(long long)(gm+8)*N+gn+1] = ll;
            }
        }
    }
}

// ---------------- pre-layer: residual accumulate + layernorm -> bf16 split ----------------
__global__ void preln_k(const float* __restrict__ xin,
                        const float* __restrict__ w, const float* __restrict__ b,
                        int first)
{
    __shared__ float sh[16];
    const int r = blockIdx.x, tid = threadIdx.x;
    const float* xr = xin + (long long)r*DM;
    float v0 = xr[tid], v1 = xr[tid+256];
    float* rr = g_res + (long long)r*DM;
    if (first) { rr[tid] = v0; rr[tid+256] = v1; }
    else       { rr[tid] += v0; rr[tid+256] += v1; }
    float s = v0+v1, ss = v0*v0 + v1*v1;
    #pragma unroll
    for (int o = 16; o > 0; o >>= 1) {
        s  += __shfl_xor_sync(0xffffffffu, s,  o);
        ss += __shfl_xor_sync(0xffffffffu, ss, o);
    }
    if ((tid & 31) == 0) { sh[tid>>5] = s; sh[8 + (tid>>5)] = ss; }
    __syncthreads();
    if (tid == 0) {
        float a = 0.f, bb = 0.f;
        for (int i = 0; i < 8; i++) { a += sh[i]; bb += sh[8+i]; }
        sh[0] = a; sh[8] = bb;
    }
    __syncthreads();
    float m    = sh[0] * (1.f/DM);
    float var  = sh[8] * (1.f/DM) - m*m;
    float rstd = rsqrtf(var + 1e-5f);
    float o0 = (v0 - m)*rstd*w[tid]     + b[tid];
    float o1 = (v1 - m)*rstd*w[tid+256] + b[tid+256];
    __nv_bfloat16 hh, ll;
    bsplit(o0, hh, ll); a_xn_h[(long long)r*DM+tid]     = hh; a_xn_l[(long long)r*DM+tid]     = ll;
    bsplit(o1, hh, ll); a_xn_h[(long long)r*DM+tid+256] = hh; a_xn_l[(long long)r*DM+tid+256] = ll;
}

// ---------------- final: x + residual -> layernorm -> out ----------------
__global__ void final_k(const float* __restrict__ w, const float* __restrict__ b,
                        float* __restrict__ out)
{
    __shared__ float sh[16];
    const int r = blockIdx.x, tid = threadIdx.x;
    float v0 = g_x[(long long)r*DM + tid]       + g_res[(long long)r*DM + tid];
    float v1 = g_x[(long long)r*DM + tid + 256] + g_res[(long long)r*DM + tid + 256];
    float s = v0+v1, ss = v0*v0 + v1*v1;
    #pragma unroll
    for (int o = 16; o > 0; o >>= 1) {
        s  += __shfl_xor_sync(0xffffffffu, s,  o);
        ss += __shfl_xor_sync(0xffffffffu, ss, o);
    }
    if ((tid & 31) == 0) { sh[tid>>5] = s; sh[8 + (tid>>5)] = ss; }
    __syncthreads();
    if (tid == 0) {
        float a = 0.f, bb = 0.f;
        for (int i = 0; i < 8; i++) { a += sh[i]; bb += sh[8+i]; }
        sh[0] = a; sh[8] = bb;
    }
    __syncthreads();
    float m    = sh[0] * (1.f/DM);
    float var  = sh[8] * (1.f/DM) - m*m;
    float rstd = rsqrtf(var + 1e-5f);
    out[(long long)r*DM + tid]       = (v0 - m)*rstd*w[tid]     + b[tid];
    out[(long long)r*DM + tid + 256] = (v1 - m)*rstd*w[tid+256] + b[tid+256];
}

// ---------------- depthwise causal conv (width 4) + bias + silu ----------------
__global__ void conv_silu_k(const float* __restrict__ cw, const float* __restrict__ cb)
{
    int idx = blockIdx.x * blockDim.x + threadIdx.x;
    int dir = idx >> 21;
    int rem = idx & ((1<<21) - 1);
    int row = rem >> 10;
    int c   = rem & (DIN-1);
    int t   = row & (LQ-1);
    const float* base = g_xz + (long long)dir*BLQ*2*DIN;
    float acc = cb[dir*DIN + c];
    const float* wc = cw + (dir*DIN + c)*4;
    #pragma unroll
    for (int j = 0; j < 4; j++) {
        int tt = t - 3 + j;
        if (tt >= 0) acc = fmaf(wc[j], base[(long long)(row - 3 + j)*(2*DIN) + c], acc);
    }
    acc = acc / (1.f + __expf(-acc));
    long long o = (long long)dir*BLQ*DIN + (long long)row*DIN + c;
    g_xcs[o] = acc;
    __nv_bfloat16 hh, ll; bsplit(acc, hh, ll);
    a_xcs_h[o] = hh; a_xcs_l[o] = ll;
}

// ---------------- selective scan: depth-2 prefetch, 16 lanes/channel ----------------
__global__ void scan_k(const float* __restrict__ A_log, const float* __restrict__ Dp)
{
    int gtid = blockIdx.x * blockDim.x + threadIdx.x;
    int warp = gtid >> 5;
    int lane = threadIdx.x & 31;
    int half = lane >> 4;
    int n    = lane & 15;
    int ch   = warp*2 + half;
    int dir  = ch >> 11;
    int bc   = ch & 2047;
    int b    = bc >> 10;
    int c    = bc & (DIN-1);

    const float An = -__expf(A_log[((long long)dir*DIN + c)*DSN + n]);
    const float Dv = Dp[dir*DIN + c];
    const long long rbase = (long long)b * LQ;

    const float* dtp = g_dt   + (long long)dir*BLQ*DIN   + rbase*DIN   + c;
    const float* up  = g_xcs  + (long long)dir*BLQ*DIN   + rbase*DIN   + c;
    const float* Bp  = g_xdbl + (long long)dir*BLQ*64    + rbase*64    + RKQ + n;
    const float* Cpp = Bp + DSN;
    const float* zp  = g_xz   + (long long)dir*BLQ*2*DIN + rbase*2*DIN + DIN + c;
    __nv_bfloat16* yh = a_y_h + (long long)dir*BLQ*DIN + rbase*DIN + c;
    __nv_bfloat16* yl = a_y_l + (long long)dir*BLQ*DIN + rbase*DIN + c;

    const bool em = (n == 0);

    // depth-2 prefetch registers
    float d0 = __ldg(dtp),        u0 = __ldg(up);
    float B0 = __ldg(Bp),         C0 = __ldg(Cpp);
    float z0 = em ? __ldg(zp) : 0.f;
    float d1 = __ldg(dtp + DIN),  u1 = __ldg(up + DIN);
    float B1 = __ldg(Bp + 64),    C1 = __ldg(Cpp + 64);
    float z1 = em ? __ldg(zp + 2*DIN) : 0.f;

    const float* dtf = dtp + 2*DIN;
    const float* uf  = up  + 2*DIN;
    const float* Bf  = Bp  + 2*64;
    const float* Cf  = Cpp + 2*64;
    const float* zf  = zp  + 4*DIN;

    float h = 0.f;
    #pragma unroll 4
    for (int t = 0; t < LQ; t++) {
        float d2 = 0.f, u2 = 0.f, B2 = 0.f, C2 = 0.f, z2 = 0.f;
        if (t < LQ - 2) {
            d2 = __ldg(dtf); u2 = __ldg(uf);
            B2 = __ldg(Bf);  C2 = __ldg(Cf);
            if (em) z2 = __ldg(zf);
            dtf += DIN; uf += DIN; Bf += 64; Cf += 64; zf += 2*DIN;
        }
        float dA = __expf(d0 * An);
        h = fmaf(dA, h, d0*u0*B0);
        float p = h * C0;
        p += __shfl_xor_sync(0xffffffffu, p, 8, 16);
        p += __shfl_xor_sync(0xffffffffu, p, 4, 16);
        p += __shfl_xor_sync(0xffffffffu, p, 2, 16);
        p += __shfl_xor_sync(0xffffffffu, p, 1, 16);
        if (em) {
            float y = fmaf(u0, Dv, p);
            y *= z0 / (1.f + __expf(-z0));
            __nv_bfloat16 hh, ll; bsplit(y, hh, ll);
            yh[(long long)t*DIN] = hh;
            yl[(long long)t*DIN] = ll;
        }
        d0 = d1; u0 = u1; B0 = B1; C0 = C1; z0 = z1;
        d1 = d2; u1 = u2; B1 = B2; C1 = C2; z1 = z2;
    }
}

// ---------------- host orchestration ----------------
extern "C" void kernel_launch(void* const* d_in, const int* in_sizes, int n_in,
                              void* d_out, int out_size)
{
    const float* x        = (const float*)d_in[0];
    const float* in_w     = (const float*)d_in[1];
    const float* conv_w   = (const float*)d_in[2];
    const float* conv_b   = (const float*)d_in[3];
    const float* xp_w     = (const float*)d_in[4];
    const float* dtp_w    = (const float*)d_in[5];
    const float* dtp_b    = (const float*)d_in[6];
    const float* A_log    = (const float*)d_in[7];
    const float* D_param  = (const float*)d_in[8];
    const float* out_w    = (const float*)d_in[9];
    const float* ln_w     = (const float*)d_in[10];
    const float* ln_b     = (const float*)d_in[11];
    const float* fn_w     = (const float*)d_in[12];
    const float* fn_b     = (const float*)d_in[13];
    float* out = (float*)d_out;

    float *p_x, *p_xz, *p_xcs, *p_xdbl, *p_dt;
    cudaGetSymbolAddress((void**)&p_x,    g_x);
    cudaGetSymbolAddress((void**)&p_xz,   g_xz);
    cudaGetSymbolAddress((void**)&p_xcs,  g_xcs);
    cudaGetSymbolAddress((void**)&p_xdbl, g_xdbl);
    cudaGetSymbolAddress((void**)&p_dt,   g_dt);

    __nv_bfloat16 *pw_in_h, *pw_in_l, *pw_xp_h, *pw_xp_l, *pw_dt_h, *pw_dt_l, *pw_out_h, *pw_out_l;
    __nv_bfloat16 *pa_xn_h, *pa_xn_l, *pa_xcs_h, *pa_xcs_l, *pa_xd_h, *pa_xd_l, *pa_y_h, *pa_y_l;
    cudaGetSymbolAddress((void**)&pw_in_h,  w_in_h);  cudaGetSymbolAddress((void**)&pw_in_l,  w_in_l);
    cudaGetSymbolAddress((void**)&pw_xp_h,  w_xp_h);  cudaGetSymbolAddress((void**)&pw_xp_l,  w_xp_l);
    cudaGetSymbolAddress((void**)&pw_dt_h,  w_dt_h);  cudaGetSymbolAddress((void**)&pw_dt_l,  w_dt_l);
    cudaGetSymbolAddress((void**)&pw_out_h, w_out_h); cudaGetSymbolAddress((void**)&pw_out_l, w_out_l);
    cudaGetSymbolAddress((void**)&pa_xn_h,  a_xn_h);  cudaGetSymbolAddress((void**)&pa_xn_l,  a_xn_l);
    cudaGetSymbolAddress((void**)&pa_xcs_h, a_xcs_h); cudaGetSymbolAddress((void**)&pa_xcs_l, a_xcs_l);
    cudaGetSymbolAddress((void**)&pa_xd_h,  a_xd_h);  cudaGetSymbolAddress((void**)&pa_xd_l,  a_xd_l);
    cudaGetSymbolAddress((void**)&pa_y_h,   a_y_h);   cudaGetSymbolAddress((void**)&pa_y_l,   a_y_l);

    // smem opt-in for all GEMM configs used
    cudaFuncSetAttribute((const void*)gemm_bf<2,4,2,4, 1,0,1,0>, cudaFuncAttributeMaxDynamicSharedMemorySize, 61440);
    cudaFuncSetAttribute((const void*)gemm_bf<2,2,1,4, 0,0,1,1>, cudaFuncAttributeMaxDynamicSharedMemorySize, 30720);
    cudaFuncSetAttribute((const void*)gemm_bf<2,4,2,2, 0,1,1,0>, cudaFuncAttributeMaxDynamicSharedMemorySize, 40960);
    cudaFuncSetAttribute((const void*)gemm_bf<2,4,2,2, 0,0,2,0>, cudaFuncAttributeMaxDynamicSharedMemorySize, 40960);

    split_k<<<1024, 256>>>(in_w,  pw_in_h,  pw_in_l,  SZ_IN);
    split_k<<<512,  256>>>(xp_w,  pw_xp_h,  pw_xp_l,  SZ_XP);
    split_k<<<256,  256>>>(dtp_w, pw_dt_h,  pw_dt_l,  SZ_DT);
    split_k<<<1024, 256>>>(out_w, pw_out_h, pw_out_l, SZ_OUT);

    for (int l = 0; l < NLAY; l++) {
        preln_k<<<BLQ, 256>>>(l == 0 ? x : p_x, ln_w + l*DM, ln_b + l*DM, l == 0);

        // in_proj: M=2048 N=2048 K=512  tile 64x128 -> 1024 CTAs
        gemm_bf<2,4,2,4, 1,0,1,0><<<dim3(16,32,2), 256, 61440>>>(
            pa_xn_h, pa_xn_l, 0LL, 0LL, DM,
            pw_in_h + (long long)l*2*2*DIN*DM, pw_in_l + (long long)l*2*2*DIN*DM,
            (long long)2*DIN*DM, 0LL,
            nullptr, 0LL,
            p_xz, (long long)BLQ*2*DIN, nullptr, nullptr,
            BLQ, 2*DIN, DM);

        conv_silu_k<<<(2*BLQ*DIN)/256, 256>>>(conv_w + l*2*DIN*4, conv_b + l*2*DIN);

        // x_proj: M=2048 N=64 K=1024  tile 32x64 -> 128 CTAs (+ split out)
        gemm_bf<2,2,1,4, 0,0,1,1><<<dim3(1,64,2), 128, 30720>>>(
            pa_xcs_h, pa_xcs_l, (long long)BLQ*DIN, 0LL, DIN,
            pw_xp_h + (long long)l*2*64*DIN, pw_xp_l + (long long)l*2*64*DIN,
            (long long)64*DIN, 0LL,
            nullptr, 0LL,
            p_xdbl, (long long)BLQ*64, pa_xd_h, pa_xd_l,
            BLQ, 64, DIN);

        // dt_proj: M=2048 N=1024 K=32  tile 64x64 -> 1024 CTAs
        gemm_bf<2,4,2,2, 0,1,1,0><<<dim3(16,32,2), 256, 40960>>>(
            pa_xd_h, pa_xd_l, (long long)BLQ*64, 0LL, 64,
            pw_dt_h + (long long)l*2*DIN*RKQ, pw_dt_l + (long long)l*2*DIN*RKQ,
            (long long)DIN*RKQ, 0LL,
            dtp_b + (long long)l*2*DIN, (long long)DIN,
            p_dt, (long long)BLQ*DIN, nullptr, nullptr,
            BLQ, DIN, RKQ);

        scan_k<<<256, 256>>>(A_log + (long long)l*2*DIN*DSN, D_param + l*2*DIN);

        // out_proj: M=2048 N=512 K=1024x2 segs  tile 64x64 -> 256 CTAs
        gemm_bf<2,4,2,2, 0,0,2,0><<<dim3(8,32,1), 256, 40960>>>(
            pa_y_h, pa_y_l, 0LL, (long long)BLQ*DIN, DIN,
            pw_out_h + (long long)l*2*DM*DIN, pw_out_l + (long long)l*2*DM*DIN,
            0LL, (long long)DM*DIN,
            nullptr, 0LL,
            p_x, 0LL, nullptr, nullptr,
            BLQ, DM, DIN);
    }

    final_k<<<BLQ, 256>>>(fn_w, fn_b, out);
}